// round 11
// baseline (speedup 1.0000x reference)
#include <cuda_runtime.h>
#include <cmath>

#define KMAX 100
#define NBKT 256
#define WPB  8      // warps per block, one (n,c) problem per warp (2 per SMSP)
#define TRN  128    // tranche size (candidates per NMS round)
#define SPT  4      // candidates per lane (TRN/32)

// Scratch (device globals — no allocation allowed).
__device__ float    g_flat_scores[16 * 128 * KMAX];     // [N][C][K]
__device__ float    g_flat_boxes [16 * 128 * KMAX * 4]; // [N][C][K][4]
__device__ float    g_conf_t     [16 * 128 * 1024];     // [N][C][B] transposed
__device__ unsigned g_hist       [16 * NBKT];           // per-image score hist

// ---------------------------------------------------------------------------
// Transpose conf [N][B][C+1] -> g_conf_t [N][C][B]  (drop background column)
// Also: rois passthrough + zero g_hist for the decode-built histograms.
// ---------------------------------------------------------------------------
__global__ void transpose_conf_kernel(const float* __restrict__ conf,
                                      const float4* __restrict__ rois4,
                                      float4* __restrict__ out_rois4,
                                      int rois_vec4, int B, int C)
{
    __shared__ float tile[32][33];
    const int n  = blockIdx.z;
    const int b0 = blockIdx.x * 32;
    const int c0 = blockIdx.y * 32;
    const int tx = threadIdx.x, ty = threadIdx.y;   // (32, 8)
    const int tid = ty * 32 + tx;

    // rois passthrough, spread over the by==0 slice of the grid
    if (blockIdx.y == 0) {
        int flat = (blockIdx.z * gridDim.x + blockIdx.x) * 256 + tid;
        if (flat < rois_vec4) out_rois4[flat] = rois4[flat];
    }
    // zero per-image histogram (one block per image does it)
    if (blockIdx.x == 0 && blockIdx.y == 0 && tid < NBKT)
        g_hist[n * NBKT + tid] = 0u;

    #pragma unroll
    for (int s = 0; s < 4; s++) {
        int b = b0 + ty + s * 8;
        int c = c0 + tx;
        if (b < B && c < C)
            tile[ty + s * 8][tx] = conf[((size_t)n * B + b) * (C + 1) + c];
    }
    __syncthreads();
    #pragma unroll
    for (int s = 0; s < 4; s++) {
        int c = c0 + ty + s * 8;
        int b = b0 + tx;
        if (b < B && c < C)
            g_conf_t[((size_t)n * C + c) * B + b] = tile[tx][ty + s * 8];
    }
}

// ---------------------------------------------------------------------------
// Warp-parallel threshold pickers over a 256-bucket histogram.
// ---------------------------------------------------------------------------
__device__ __forceinline__ int pick_window_le(const unsigned* hist, int t_hi,
                                              int limit, int lane, int* cnt_out)
{
    const unsigned FULL = 0xffffffffu;
    unsigned s = 0;
    #pragma unroll
    for (int m = 0; m < 8; m++) {
        int k = 8 * lane + m;
        if (k < t_hi) s += hist[k];
    }
    unsigned cum = s;                                // suffix-inclusive scan
    #pragma unroll
    for (int off = 1; off < 32; off <<= 1) {
        unsigned o = __shfl_down_sync(FULL, cum, off);
        if (lane + off < 32) cum += o;
    }
    unsigned bal = __ballot_sync(FULL, cum <= (unsigned)limit);
    int t_lo, cnt;
    int l0 = (bal == 0) ? 32 : (__ffs(bal) - 1);
    if (l0 == 0) {
        t_lo = 0;
        cnt  = (int)__shfl_sync(FULL, cum, 0);
    } else {
        int rl = (l0 - 1 < 31) ? l0 - 1 : 31;
        unsigned below = (l0 <= 31) ? __shfl_sync(FULL, cum, l0) : 0u;
        if (l0 == 32) below = 0u;
        int tl = (8 * l0 < 256) ? 8 * l0 : 256;
        unsigned run = below;
        if (lane == rl) {
            #pragma unroll
            for (int m = 7; m >= 0; m--) {
                int k = 8 * rl + m;
                unsigned h = (k < t_hi) ? hist[k] : 0u;
                if (run + h <= (unsigned)limit) { run += h; tl = k; }
                else break;
            }
        }
        t_lo = __shfl_sync(FULL, tl, rl);
        cnt  = (int)__shfl_sync(FULL, run, rl);
    }
    if (t_lo >= t_hi) {          // even one bucket overflows: take it anyway
        t_lo = t_hi - 1;
        cnt  = (int)hist[t_lo];
    }
    *cnt_out = cnt;
    return t_lo;
}

__device__ __forceinline__ int pick_window_ge(const unsigned* hist, int limit,
                                              int lane, int* cnt_out)
{
    const unsigned FULL = 0xffffffffu;
    unsigned s = 0;
    #pragma unroll
    for (int m = 0; m < 8; m++) s += hist[8 * lane + m];
    unsigned cum = s;
    #pragma unroll
    for (int off = 1; off < 32; off <<= 1) {
        unsigned o = __shfl_down_sync(FULL, cum, off);
        if (lane + off < 32) cum += o;
    }
    unsigned bal = __ballot_sync(FULL, cum >= (unsigned)limit);
    int t_lo, cnt;
    if (bal == 0) {
        t_lo = 0;
        cnt  = (int)__shfl_sync(FULL, cum, 0);
    } else {
        int lp = 31 - __clz(bal);
        unsigned below = (lp < 31) ? __shfl_sync(FULL, cum, lp + 1) : 0u;
        int tl = 8 * (lp + 1);
        unsigned run = below;
        if (lane == lp) {
            #pragma unroll
            for (int m = 7; m >= 0; m--) {
                run += hist[8 * lp + m];
                tl = 8 * lp + m;
                if (run >= (unsigned)limit) break;
            }
        }
        t_lo = __shfl_sync(FULL, tl, lp);
        cnt  = (int)__shfl_sync(FULL, run, lp);
    }
    *cnt_out = cnt;
    return t_lo;
}

// ---------------------------------------------------------------------------
// Stage 1: one WARP per (n, c); 8 warps per 256-thread CTA.
// score load -> histogram -> threshold -> ballot compact (<=128) ->
// bitonic sort -> gather-decode (interleaved ranks) -> upper-triangle
// suppression-mask matrix -> lane-0 64-bit bit-scan -> parallel epilogue
// (which also accumulates the per-image global histogram for stage 2).
// ---------------------------------------------------------------------------
__global__ __launch_bounds__(32 * WPB)
void decode_nms_kernel(const float* __restrict__ rois,
                       const float* __restrict__ deltas,
                       int B, int C, int NC, float hm1, float wm1)
{
    const int w    = threadIdx.x >> 5;
    const int lane = threadIdx.x & 31;
    const int pid  = blockIdx.x * WPB + w;
    if (pid >= NC) return;
    const int n = pid / C;
    const int c = pid % C;
    const unsigned FULL = 0xffffffffu;

    __shared__ unsigned           hist_s [WPB][NBKT];
    __shared__ unsigned long long ckey_s [WPB][TRN];
    __shared__ float4             rbox_s [WPB][TRN];
    __shared__ float              rarea_s[WPB][TRN];
    __shared__ uint4              mask_s [WPB][TRN];
    __shared__ float4             kbox_s [WPB][KMAX];
    __shared__ float              karea_s[WPB][KMAX];
    __shared__ int                sidx_s [WPB][KMAX];

    unsigned*           hist  = hist_s [w];
    unsigned long long* ckey  = ckey_s [w];
    float4*             rbox  = rbox_s [w];
    float*              rarea = rarea_s[w];
    uint4*              maskm = mask_s [w];
    float4*             kbox  = kbox_s [w];
    float*              karea = karea_s[w];
    int*                sidx  = sidx_s [w];

    for (int i = lane; i < NBKT; i += 32) hist[i] = 0u;
    __syncwarp();

    // ---- coalesced score load (transposed conf), MLP=8 ----
    const float* csrc = g_conf_t + ((size_t)n * C + c) * B;
    const int NV4 = B >> 2;          // B divisible by 4 (B=1000)
    float rs[32];
    #pragma unroll
    for (int u = 0; u < 8; u++) {
        int i4 = lane + 32 * u;
        float4 v = make_float4(0.f, 0.f, 0.f, 0.f);
        if (i4 < NV4) v = ((const float4*)csrc)[i4];
        rs[4*u+0] = (v.x > 0.05f) ? v.x : 0.f;
        rs[4*u+1] = (v.y > 0.05f) ? v.y : 0.f;
        rs[4*u+2] = (v.z > 0.05f) ? v.z : 0.f;
        rs[4*u+3] = (v.w > 0.05f) ? v.w : 0.f;
    }
    // b index of rs[e]: e = 4u + j  ->  b = 128*u + 4*lane + j

    #pragma unroll
    for (int e = 0; e < 32; e++) {
        float v = rs[e];
        if (v > 0.f) atomicAdd(&hist[min((int)(v * 256.f), 255)], 1u);
    }
    __syncwarp();

    float* fs = g_flat_scores + ((size_t)n * C + c) * KMAX;
    float* fb = g_flat_boxes  + ((size_t)n * C + c) * KMAX * 4;
    unsigned* ghist = g_hist + n * NBKT;

    int kept = 0;
    int t_hi = NBKT;

    while (kept < KMAX && t_hi > 0) {
        int cnt;
        const int t_lo = pick_window_le(hist, t_hi, TRN, lane, &cnt);
        const int w_hi = t_hi;          // window = [t_lo, w_hi)
        t_hi = t_lo;
        if (cnt > TRN) cnt = TRN;
        if (cnt == 0) continue;

        // ---- ballot compaction ----
        unsigned base = 0;
        #pragma unroll
        for (int e = 0; e < 32; e++) {
            float v = rs[e];
            int bk = (v > 0.f) ? min((int)(v * 256.f), 255) : -1;
            bool take = (bk >= t_lo) && (bk < w_hi);
            unsigned m = __ballot_sync(FULL, take);
            if (take) {
                unsigned pos = base + __popc(m & ((1u << lane) - 1u));
                if (pos < (unsigned)TRN) {
                    int b = 128 * (e >> 2) + 4 * lane + (e & 3);
                    ckey[pos] = ((unsigned long long)__float_as_uint(v) << 10)
                              | (unsigned long long)(1023 - b);
                }
            }
            base += __popc(m);
        }
        __syncwarp();

        int P = 1; while (P < cnt) P <<= 1;
        for (int i = cnt + lane; i < P; i += 32) ckey[i] = 0ull;
        __syncwarp();

        // ---- bitonic sort desc by (score, ~b) ----
        for (int k = 2; k <= P; k <<= 1) {
            for (int j = k >> 1; j > 0; j >>= 1) {
                for (int p = lane; p < (P >> 1); p += 32) {
                    int i = ((p & ~(j - 1)) << 1) | (p & (j - 1));
                    int l = i | j;
                    unsigned long long a = ckey[i], bb = ckey[l];
                    bool desc = ((i & k) == 0);
                    if (desc ? (a < bb) : (a > bb)) { ckey[i] = bb; ckey[l] = a; }
                }
                __syncwarp();
            }
        }

        // ---- gather-decode: INTERLEAVED ranks, lane owns r = lane + 32q ----
        float by1[SPT], bx1[SPT], by2[SPT], bx2[SPT], bar_[SPT];
        unsigned alive = 0;
        #pragma unroll
        for (int q = 0; q < SPT; q++) {
            int r = lane + 32 * q;
            float yy1 = 0.f, xx1 = 0.f, yy2 = 0.f, xx2 = 0.f, ar = 0.f;
            if (r < cnt) {
                unsigned long long key = ckey[r];
                int b = 1023 - (int)(key & 1023ull);
                float4 rr = ((const float4*)rois)[(size_t)n * B + b];
                float w0 = rr.w - rr.y + 1.0f;
                float h0 = rr.z - rr.x + 1.0f;
                float x0 = rr.y + 0.5f * w0;
                float y0 = rr.x + 0.5f * h0;
                float4 d = ((const float4*)deltas)[((size_t)n * B + b) * C + c];
                float cx = (d.x * 0.1f) * w0 + x0;
                float cy = (d.y * 0.1f) * h0 + y0;
                float ww = __expf(d.z * 0.2f) * w0;
                float hh = __expf(d.w * 0.2f) * h0;
                xx1 = fminf(fmaxf(cx - 0.5f * ww, 0.0f), wm1);
                yy1 = fminf(fmaxf(cy - 0.5f * hh, 0.0f), hm1);
                xx2 = fminf(fmaxf(cx + 0.5f * ww, 0.0f), wm1);
                yy2 = fminf(fmaxf(cy + 0.5f * hh, 0.0f), hm1);
                ar  = (yy2 - yy1) * (xx2 - xx1);
                rbox[r]  = make_float4(yy1, xx1, yy2, xx2);
                rarea[r] = ar;
                alive |= (1u << q);
            }
            by1[q] = yy1; bx1[q] = xx1; by2[q] = yy2; bx2[q] = xx2; bar_[q] = ar;
        }
        __syncwarp();

        // ---- later tranches: pre-suppress vs already-kept boxes ----
        for (int kk = 0; kk < kept; kk++) {
            float4 kb = kbox[kk];
            float  ka = karea[kk];
            #pragma unroll
            for (int q = 0; q < SPT; q++) {
                if (alive & (1u << q)) {
                    float iy1 = fmaxf(kb.x, by1[q]);
                    float ix1 = fmaxf(kb.y, bx1[q]);
                    float iy2 = fminf(kb.z, by2[q]);
                    float ix2 = fminf(kb.w, bx2[q]);
                    float it  = fmaxf(iy2 - iy1, 0.f) * fmaxf(ix2 - ix1, 0.f);
                    float un  = fmaxf(ka + bar_[q] - it, 1e-8f);
                    if (it > 0.5f * un) alive &= ~(1u << q);
                }
            }
        }

        // ---- upper-triangle suppression-mask matrix ----
        unsigned acc[SPT][4];
        #pragma unroll
        for (int q = 0; q < SPT; q++) {
            acc[q][0] = 0u; acc[q][1] = 0u; acc[q][2] = 0u; acc[q][3] = 0u;
        }
        #pragma unroll
        for (int wb = 0; wb < 4; wb++) {
            if (32 * wb >= cnt) break;
            #pragma unroll 4
            for (int sb = 0; sb < 32; sb++) {
                int s = 32 * wb + sb;
                float4 bs = rbox[s];          // broadcast LDS
                float  as_ = rarea[s];
                #pragma unroll
                for (int q = 0; q <= wb && q < SPT; q++) {
                    float iy1 = fmaxf(bs.x, by1[q]);
                    float ix1 = fmaxf(bs.y, bx1[q]);
                    float iy2 = fminf(bs.z, by2[q]);
                    float ix2 = fminf(bs.w, bx2[q]);
                    float it  = fmaxf(iy2 - iy1, 0.f) * fmaxf(ix2 - ix1, 0.f);
                    float un  = fmaxf(as_ + bar_[q] - it, 1e-8f);
                    bool sup  = (it > 0.5f * un);
                    if (q == wb) sup = sup || (sb == lane);   // self-bit
                    if (sup) acc[q][wb] |= (1u << sb);
                }
            }
        }
        #pragma unroll
        for (int q = 0; q < SPT; q++)
            maskm[lane + 32 * q] =
                make_uint4(acc[q][0], acc[q][1], acc[q][2], acc[q][3]);
        __syncwarp();

        // ---- alive words via ballot (word q = ranks [32q, 32q+32)) ----
        unsigned a0 = __ballot_sync(FULL, (alive >> 0) & 1u);
        unsigned a1 = __ballot_sync(FULL, (alive >> 1) & 1u);
        unsigned a2 = __ballot_sync(FULL, (alive >> 2) & 1u);
        unsigned a3 = __ballot_sync(FULL, (alive >> 3) & 1u);

        // ---- serial 64-bit bit-scan on lane 0 (ffsll -> LDS.128 -> AND) ----
        int kn = 0;
        if (lane == 0) {
            unsigned long long A0 = (unsigned long long)a0
                                  | ((unsigned long long)a1 << 32);
            unsigned long long A1 = (unsigned long long)a2
                                  | ((unsigned long long)a3 << 32);
            const int room = KMAX - kept;
            while (kn < room) {
                int r;
                if (A0)      r = __ffsll(A0) - 1;
                else if (A1) r = 63 + __ffsll(A1);
                else break;
                sidx[kn++] = r;
                uint4 m = maskm[r];        // LDS.128 (has self-bit)
                A0 &= ~((unsigned long long)m.x
                        | ((unsigned long long)m.y << 32));
                A1 &= ~((unsigned long long)m.z
                        | ((unsigned long long)m.w << 32));
            }
        }
        kn = __shfl_sync(FULL, kn, 0);

        // ---- parallel output epilogue + per-image histogram accumulate ----
        for (int i = lane; i < kn; i += 32) {
            int r = sidx[i];
            float4 bb = rbox[r];
            float  v  = __uint_as_float((unsigned)(ckey[r] >> 10));
            fs[kept + i] = v;
            ((float4*)fb)[kept + i] = bb;
            kbox[kept + i]  = bb;
            karea[kept + i] = rarea[r];
            atomicAdd(&ghist[min((int)(v * 256.f), 255)], 1u);
        }
        kept += kn;
        __syncwarp();
    }

    for (int kk = kept + lane; kk < KMAX; kk += 32) fs[kk] = 0.0f;
}

// ---------------------------------------------------------------------------
// Stage 2: per image, exact rank-100. Histogram precomputed by decode.
// Warp-aggregated compaction + rank-by-count ordering (no bitonic sort,
// 3 barriers total). Keys unique (index in low bits) -> rank is a perm.
// ---------------------------------------------------------------------------
__global__ __launch_bounds__(512)
void topk_kernel(float* __restrict__ out_boxes,
                 float* __restrict__ out_scores,
                 float* __restrict__ out_classes,
                 float* __restrict__ out_numdets,
                 int C)
{
    const int n    = blockIdx.x;
    const int tid  = threadIdx.x;
    const int lane = tid & 31;
    const int CK   = C * KMAX;                 // 8000
    const unsigned FULL = 0xffffffffu;

    __shared__ unsigned           hist[NBKT];
    __shared__ unsigned long long key[1024];
    __shared__ unsigned long long sorted[KMAX];
    __shared__ unsigned           scnt;

    // load precomputed per-image histogram
    if (tid < NBKT) hist[tid] = g_hist[n * NBKT + tid];
    if (tid == 0) scnt = 0u;
    if (tid < KMAX) sorted[tid] = 0ull;

    // batched score loads while histogram settles
    const float* src = g_flat_scores + (size_t)n * CK;
    const int NV4 = CK >> 2;                   // 2000
    float4 v4[4];
    #pragma unroll
    for (int u = 0; u < 4; u++) {
        int i4 = tid + 512 * u;
        v4[u] = (i4 < NV4) ? ((const float4*)src)[i4]
                           : make_float4(0.f, 0.f, 0.f, 0.f);
    }
    __syncthreads();

    int cnt_est;
    const int t_lo = pick_window_ge(hist, KMAX, lane, &cnt_est);  // all warps same

    // ---- warp-aggregated compaction ----
    #pragma unroll
    for (int u = 0; u < 4; u++) {
        float vv[4] = {v4[u].x, v4[u].y, v4[u].z, v4[u].w};
        #pragma unroll
        for (int j = 0; j < 4; j++) {
            float v = vv[j];
            bool take = (v > 0.f) && (min((int)(v * 256.f), 255) >= t_lo);
            unsigned m = __ballot_sync(FULL, take);
            if (m) {
                int leader = __ffs(m) - 1;
                unsigned base = 0;
                if (lane == leader) base = atomicAdd(&scnt, __popc(m));
                base = __shfl_sync(FULL, base, leader);
                if (take) {
                    unsigned p = base + __popc(m & ((1u << lane) - 1u));
                    if (p < 1024u) {
                        int i = 4 * (tid + 512 * u) + j;
                        key[p] = ((unsigned long long)__float_as_uint(v) << 13)
                               | (unsigned long long)(8191 - i);
                    }
                }
            }
        }
    }
    __syncthreads();
    const int cnt = min((int)scnt, 1024);

    // ---- rank-by-count ordering (no barriers inside) ----
    #pragma unroll
    for (int o = 0; o < 2; o++) {
        int own = tid + 512 * o;
        if (own < cnt) {
            unsigned long long mykey = key[own];
            int rank = 0;
            for (int s = 0; s < cnt; s++)
                rank += (key[s] > mykey) ? 1 : 0;
            if (rank < KMAX) sorted[rank] = mykey;
        }
    }
    __syncthreads();

    if (tid < KMAX) {
        unsigned long long kk = sorted[tid];
        bool valid = (kk != 0ull);
        float s = __uint_as_float((unsigned)(kk >> 13));
        int  fi = 8191 - (int)(kk & 8191ull);
        out_scores [n * KMAX + tid] = valid ? s : 0.f;
        out_classes[n * KMAX + tid] = valid ? (float)(fi / KMAX) : 0.f;
        float4 bb = make_float4(0.f, 0.f, 0.f, 0.f);
        if (valid) bb = ((const float4*)g_flat_boxes)[(size_t)n * CK + fi];
        ((float4*)out_boxes)[n * KMAX + tid] = bb;
    }
    if (tid == 0) out_numdets[n] = (float)min(cnt, KMAX);
}

// ---------------------------------------------------------------------------
extern "C" void kernel_launch(void* const* d_in, const int* in_sizes, int n_in,
                              void* d_out, int out_size)
{
    const float* rois   = (const float*)d_in[0];
    const float* conf   = (const float*)d_in[1];
    const float* deltas = (const float*)d_in[2];

    const int rois_elems = in_sizes[0];
    const int N = (out_size - rois_elems) / (6 * KMAX + 1);
    const int B = rois_elems / (4 * N);
    const int C = in_sizes[2] / ((size_t)N * B * 4);
    const int HW = in_sizes[3] / (3 * N);
    const int H = (int)(sqrt((double)HW) + 0.5);   // square image
    const float hm1 = (float)(H - 1);
    const float wm1 = (float)(H - 1);

    float* out         = (float*)d_out;
    float* out_boxes   = out;
    float* out_scores  = out + (size_t)N * KMAX * 4;
    float* out_classes = out + (size_t)N * KMAX * 5;
    float* out_numdets = out + (size_t)N * KMAX * 6;
    float* out_rois    = out + (size_t)N * KMAX * 6 + N;

    {
        dim3 grid((B + 31) / 32, (C + 31) / 32, N);
        dim3 block(32, 8);
        transpose_conf_kernel<<<grid, block>>>(conf, (const float4*)rois,
                                               (float4*)out_rois,
                                               rois_elems / 4, B, C);
    }
    {
        const int NC = N * C;
        decode_nms_kernel<<<(NC + WPB - 1) / WPB, 32 * WPB>>>(
            rois, deltas, B, C, NC, hm1, wm1);
    }
    topk_kernel<<<N, 512>>>(out_boxes, out_scores, out_classes,
                            out_numdets, C);
}

// round 12
// speedup vs baseline: 1.2109x; 1.2109x over previous
#include <cuda_runtime.h>
#include <cmath>

#define KMAX 100
#define NBKT 256
#define WPB  8      // warps per block, one (n,c) problem per warp (2 per SMSP)
#define TRN  128    // tranche size (candidates per NMS round)
#define SPT  4      // candidates per lane (TRN/32)

// Scratch (device globals — no allocation allowed).
__device__ float    g_flat_scores[16 * 128 * KMAX];     // [N][C][K]
__device__ float    g_flat_boxes [16 * 128 * KMAX * 4]; // [N][C][K][4]
__device__ float    g_conf_t     [16 * 128 * 1024];     // [N][C][B] transposed
__device__ unsigned g_hist       [16 * NBKT];           // per-image score hist

// ---------------------------------------------------------------------------
// Transpose conf [N][B][C+1] -> g_conf_t [N][C][B]  (drop background column)
// Also: rois passthrough + zero g_hist for the decode-built histograms.
// ---------------------------------------------------------------------------
__global__ void transpose_conf_kernel(const float* __restrict__ conf,
                                      const float4* __restrict__ rois4,
                                      float4* __restrict__ out_rois4,
                                      int rois_vec4, int B, int C)
{
    __shared__ float tile[32][33];
    const int n  = blockIdx.z;
    const int b0 = blockIdx.x * 32;
    const int c0 = blockIdx.y * 32;
    const int tx = threadIdx.x, ty = threadIdx.y;   // (32, 8)
    const int tid = ty * 32 + tx;

    // rois passthrough, spread over the by==0 slice of the grid
    if (blockIdx.y == 0) {
        int flat = (blockIdx.z * gridDim.x + blockIdx.x) * 256 + tid;
        if (flat < rois_vec4) out_rois4[flat] = rois4[flat];
    }
    // zero per-image histogram (one block per image does it)
    if (blockIdx.x == 0 && blockIdx.y == 0 && tid < NBKT)
        g_hist[n * NBKT + tid] = 0u;

    #pragma unroll
    for (int s = 0; s < 4; s++) {
        int b = b0 + ty + s * 8;
        int c = c0 + tx;
        if (b < B && c < C)
            tile[ty + s * 8][tx] = conf[((size_t)n * B + b) * (C + 1) + c];
    }
    __syncthreads();
    #pragma unroll
    for (int s = 0; s < 4; s++) {
        int c = c0 + ty + s * 8;
        int b = b0 + tx;
        if (b < B && c < C)
            g_conf_t[((size_t)n * C + c) * B + b] = tile[tx][ty + s * 8];
    }
}

// ---------------------------------------------------------------------------
// Warp-parallel threshold pickers over a 256-bucket histogram.
// ---------------------------------------------------------------------------
__device__ __forceinline__ int pick_window_le(const unsigned* hist, int t_hi,
                                              int limit, int lane, int* cnt_out)
{
    const unsigned FULL = 0xffffffffu;
    unsigned s = 0;
    #pragma unroll
    for (int m = 0; m < 8; m++) {
        int k = 8 * lane + m;
        if (k < t_hi) s += hist[k];
    }
    unsigned cum = s;                                // suffix-inclusive scan
    #pragma unroll
    for (int off = 1; off < 32; off <<= 1) {
        unsigned o = __shfl_down_sync(FULL, cum, off);
        if (lane + off < 32) cum += o;
    }
    unsigned bal = __ballot_sync(FULL, cum <= (unsigned)limit);
    int t_lo, cnt;
    int l0 = (bal == 0) ? 32 : (__ffs(bal) - 1);
    if (l0 == 0) {
        t_lo = 0;
        cnt  = (int)__shfl_sync(FULL, cum, 0);
    } else {
        int rl = (l0 - 1 < 31) ? l0 - 1 : 31;
        unsigned below = (l0 <= 31) ? __shfl_sync(FULL, cum, l0) : 0u;
        if (l0 == 32) below = 0u;
        int tl = (8 * l0 < 256) ? 8 * l0 : 256;
        unsigned run = below;
        if (lane == rl) {
            #pragma unroll
            for (int m = 7; m >= 0; m--) {
                int k = 8 * rl + m;
                unsigned h = (k < t_hi) ? hist[k] : 0u;
                if (run + h <= (unsigned)limit) { run += h; tl = k; }
                else break;
            }
        }
        t_lo = __shfl_sync(FULL, tl, rl);
        cnt  = (int)__shfl_sync(FULL, run, rl);
    }
    if (t_lo >= t_hi) {          // even one bucket overflows: take it anyway
        t_lo = t_hi - 1;
        cnt  = (int)hist[t_lo];
    }
    *cnt_out = cnt;
    return t_lo;
}

__device__ __forceinline__ int pick_window_ge(const unsigned* hist, int limit,
                                              int lane, int* cnt_out)
{
    const unsigned FULL = 0xffffffffu;
    unsigned s = 0;
    #pragma unroll
    for (int m = 0; m < 8; m++) s += hist[8 * lane + m];
    unsigned cum = s;
    #pragma unroll
    for (int off = 1; off < 32; off <<= 1) {
        unsigned o = __shfl_down_sync(FULL, cum, off);
        if (lane + off < 32) cum += o;
    }
    unsigned bal = __ballot_sync(FULL, cum >= (unsigned)limit);
    int t_lo, cnt;
    if (bal == 0) {
        t_lo = 0;
        cnt  = (int)__shfl_sync(FULL, cum, 0);
    } else {
        int lp = 31 - __clz(bal);
        unsigned below = (lp < 31) ? __shfl_sync(FULL, cum, lp + 1) : 0u;
        int tl = 8 * (lp + 1);
        unsigned run = below;
        if (lane == lp) {
            #pragma unroll
            for (int m = 7; m >= 0; m--) {
                run += hist[8 * lp + m];
                tl = 8 * lp + m;
                if (run >= (unsigned)limit) break;
            }
        }
        t_lo = __shfl_sync(FULL, tl, lp);
        cnt  = (int)__shfl_sync(FULL, run, lp);
    }
    *cnt_out = cnt;
    return t_lo;
}

// ---------------------------------------------------------------------------
// Stage 1: one WARP per (n, c); 8 warps per 256-thread CTA.
// score load -> histogram -> threshold -> ballot compact (<=128) ->
// bitonic sort -> gather-decode (interleaved ranks) -> STRICT-UPPER-TRIANGLE
// suppression-mask matrix -> SPARSE lane-0 scan over suppressing rows only
// (boxes are random: ~8 suppressing pairs per 128) -> fully parallel
// extraction + epilogue via prefix popcount.
// ---------------------------------------------------------------------------
__global__ __launch_bounds__(32 * WPB)
void decode_nms_kernel(const float* __restrict__ rois,
                       const float* __restrict__ deltas,
                       int B, int C, int NC, float hm1, float wm1)
{
    const int w    = threadIdx.x >> 5;
    const int lane = threadIdx.x & 31;
    const int pid  = blockIdx.x * WPB + w;
    if (pid >= NC) return;
    const int n = pid / C;
    const int c = pid % C;
    const unsigned FULL = 0xffffffffu;

    __shared__ unsigned           hist_s [WPB][NBKT];
    __shared__ unsigned long long ckey_s [WPB][TRN];
    __shared__ float4             rbox_s [WPB][TRN];
    __shared__ float              rarea_s[WPB][TRN];
    __shared__ uint4              mask_s [WPB][TRN];
    __shared__ float4             kbox_s [WPB][KMAX];
    __shared__ float              karea_s[WPB][KMAX];

    unsigned*           hist  = hist_s [w];
    unsigned long long* ckey  = ckey_s [w];
    float4*             rbox  = rbox_s [w];
    float*              rarea = rarea_s[w];
    uint4*              maskm = mask_s [w];
    float4*             kbox  = kbox_s [w];
    float*              karea = karea_s[w];

    for (int i = lane; i < NBKT; i += 32) hist[i] = 0u;
    __syncwarp();

    // ---- coalesced score load (transposed conf), MLP=8 ----
    const float* csrc = g_conf_t + ((size_t)n * C + c) * B;
    const int NV4 = B >> 2;          // B divisible by 4 (B=1000)
    float rs[32];
    #pragma unroll
    for (int u = 0; u < 8; u++) {
        int i4 = lane + 32 * u;
        float4 v = make_float4(0.f, 0.f, 0.f, 0.f);
        if (i4 < NV4) v = ((const float4*)csrc)[i4];
        rs[4*u+0] = (v.x > 0.05f) ? v.x : 0.f;
        rs[4*u+1] = (v.y > 0.05f) ? v.y : 0.f;
        rs[4*u+2] = (v.z > 0.05f) ? v.z : 0.f;
        rs[4*u+3] = (v.w > 0.05f) ? v.w : 0.f;
    }
    // b index of rs[e]: e = 4u + j  ->  b = 128*u + 4*lane + j

    #pragma unroll
    for (int e = 0; e < 32; e++) {
        float v = rs[e];
        if (v > 0.f) atomicAdd(&hist[min((int)(v * 256.f), 255)], 1u);
    }
    __syncwarp();

    float* fs = g_flat_scores + ((size_t)n * C + c) * KMAX;
    float* fb = g_flat_boxes  + ((size_t)n * C + c) * KMAX * 4;
    unsigned* ghist = g_hist + n * NBKT;

    int kept = 0;
    int t_hi = NBKT;

    while (kept < KMAX && t_hi > 0) {
        int cnt;
        const int t_lo = pick_window_le(hist, t_hi, TRN, lane, &cnt);
        const int w_hi = t_hi;          // window = [t_lo, w_hi)
        t_hi = t_lo;
        if (cnt > TRN) cnt = TRN;
        if (cnt == 0) continue;

        // ---- ballot compaction ----
        unsigned base = 0;
        #pragma unroll
        for (int e = 0; e < 32; e++) {
            float v = rs[e];
            int bk = (v > 0.f) ? min((int)(v * 256.f), 255) : -1;
            bool take = (bk >= t_lo) && (bk < w_hi);
            unsigned m = __ballot_sync(FULL, take);
            if (take) {
                unsigned pos = base + __popc(m & ((1u << lane) - 1u));
                if (pos < (unsigned)TRN) {
                    int b = 128 * (e >> 2) + 4 * lane + (e & 3);
                    ckey[pos] = ((unsigned long long)__float_as_uint(v) << 10)
                              | (unsigned long long)(1023 - b);
                }
            }
            base += __popc(m);
        }
        __syncwarp();

        int P = 1; while (P < cnt) P <<= 1;
        for (int i = cnt + lane; i < P; i += 32) ckey[i] = 0ull;
        __syncwarp();

        // ---- bitonic sort desc by (score, ~b) ----
        for (int k = 2; k <= P; k <<= 1) {
            for (int j = k >> 1; j > 0; j >>= 1) {
                for (int p = lane; p < (P >> 1); p += 32) {
                    int i = ((p & ~(j - 1)) << 1) | (p & (j - 1));
                    int l = i | j;
                    unsigned long long a = ckey[i], bb = ckey[l];
                    bool desc = ((i & k) == 0);
                    if (desc ? (a < bb) : (a > bb)) { ckey[i] = bb; ckey[l] = a; }
                }
                __syncwarp();
            }
        }

        // ---- gather-decode: INTERLEAVED ranks, lane owns r = lane + 32q ----
        float by1[SPT], bx1[SPT], by2[SPT], bx2[SPT], bar_[SPT];
        unsigned alive = 0;
        #pragma unroll
        for (int q = 0; q < SPT; q++) {
            int r = lane + 32 * q;
            float yy1 = 0.f, xx1 = 0.f, yy2 = 0.f, xx2 = 0.f, ar = 0.f;
            if (r < cnt) {
                unsigned long long key = ckey[r];
                int b = 1023 - (int)(key & 1023ull);
                float4 rr = ((const float4*)rois)[(size_t)n * B + b];
                float w0 = rr.w - rr.y + 1.0f;
                float h0 = rr.z - rr.x + 1.0f;
                float x0 = rr.y + 0.5f * w0;
                float y0 = rr.x + 0.5f * h0;
                float4 d = ((const float4*)deltas)[((size_t)n * B + b) * C + c];
                float cx = (d.x * 0.1f) * w0 + x0;
                float cy = (d.y * 0.1f) * h0 + y0;
                float ww = __expf(d.z * 0.2f) * w0;
                float hh = __expf(d.w * 0.2f) * h0;
                xx1 = fminf(fmaxf(cx - 0.5f * ww, 0.0f), wm1);
                yy1 = fminf(fmaxf(cy - 0.5f * hh, 0.0f), hm1);
                xx2 = fminf(fmaxf(cx + 0.5f * ww, 0.0f), wm1);
                yy2 = fminf(fmaxf(cy + 0.5f * hh, 0.0f), hm1);
                ar  = (yy2 - yy1) * (xx2 - xx1);
                rbox[r]  = make_float4(yy1, xx1, yy2, xx2);
                rarea[r] = ar;
                alive |= (1u << q);
            }
            by1[q] = yy1; bx1[q] = xx1; by2[q] = yy2; bx2[q] = xx2; bar_[q] = ar;
        }
        __syncwarp();

        // ---- later tranches: pre-suppress vs already-kept boxes ----
        for (int kk = 0; kk < kept; kk++) {
            float4 kb = kbox[kk];
            float  ka = karea[kk];
            #pragma unroll
            for (int q = 0; q < SPT; q++) {
                if (alive & (1u << q)) {
                    float iy1 = fmaxf(kb.x, by1[q]);
                    float ix1 = fmaxf(kb.y, bx1[q]);
                    float iy2 = fminf(kb.z, by2[q]);
                    float ix2 = fminf(kb.w, bx2[q]);
                    float it  = fmaxf(iy2 - iy1, 0.f) * fmaxf(ix2 - ix1, 0.f);
                    float un  = fmaxf(ka + bar_[q] - it, 1e-8f);
                    if (it > 0.5f * un) alive &= ~(1u << q);
                }
            }
        }

        // ---- strict-upper-triangle suppression-mask matrix (no self-bit) ----
        unsigned acc[SPT][4];
        #pragma unroll
        for (int q = 0; q < SPT; q++) {
            acc[q][0] = 0u; acc[q][1] = 0u; acc[q][2] = 0u; acc[q][3] = 0u;
        }
        #pragma unroll
        for (int wb = 0; wb < 4; wb++) {
            if (32 * wb >= cnt) break;
            #pragma unroll 4
            for (int sb = 0; sb < 32; sb++) {
                int s = 32 * wb + sb;
                float4 bs = rbox[s];          // broadcast LDS
                float  as_ = rarea[s];
                #pragma unroll
                for (int q = 0; q <= wb && q < SPT; q++) {
                    float iy1 = fmaxf(bs.x, by1[q]);
                    float ix1 = fmaxf(bs.y, bx1[q]);
                    float iy2 = fminf(bs.z, by2[q]);
                    float ix2 = fminf(bs.w, bx2[q]);
                    float it  = fmaxf(iy2 - iy1, 0.f) * fmaxf(ix2 - ix1, 0.f);
                    float un  = fmaxf(as_ + bar_[q] - it, 1e-8f);
                    if (it > 0.5f * un) acc[q][wb] |= (1u << sb);
                }
            }
        }
        // clear <= diagonal bits in the diagonal block (strict upper triangle)
        #pragma unroll
        for (int q = 0; q < SPT; q++)
            acc[q][q] &= ~((2u << lane) - 1u);

        // suppressing-row set (rows with any mask bit) + conditional store
        unsigned srow[SPT];
        #pragma unroll
        for (int q = 0; q < SPT; q++) {
            bool nz = (acc[q][0] | acc[q][1] | acc[q][2] | acc[q][3]) != 0u;
            srow[q] = __ballot_sync(FULL, nz);
            if (nz) maskm[lane + 32 * q] =
                make_uint4(acc[q][0], acc[q][1], acc[q][2], acc[q][3]);
        }
        __syncwarp();

        // ---- alive words via ballot (word q = ranks [32q, 32q+32)) ----
        unsigned a0 = __ballot_sync(FULL, (alive >> 0) & 1u);
        unsigned a1 = __ballot_sync(FULL, (alive >> 1) & 1u);
        unsigned a2 = __ballot_sync(FULL, (alive >> 2) & 1u);
        unsigned a3 = __ballot_sync(FULL, (alive >> 3) & 1u);

        // ---- SPARSE scan on lane 0: only suppressing rows, ascending ----
        if (lane == 0) {
            unsigned long long A0 = (unsigned long long)a0
                                  | ((unsigned long long)a1 << 32);
            unsigned long long A1 = (unsigned long long)a2
                                  | ((unsigned long long)a3 << 32);
            unsigned long long S0 = (unsigned long long)srow[0]
                                  | ((unsigned long long)srow[1] << 32);
            unsigned long long S1 = (unsigned long long)srow[2]
                                  | ((unsigned long long)srow[3] << 32);
            while (S0) {
                int r = __ffsll(S0) - 1;
                S0 &= S0 - 1;
                if ((A0 >> r) & 1ull) {
                    uint4 m = maskm[r];
                    A0 &= ~((unsigned long long)m.x
                            | ((unsigned long long)m.y << 32));
                    A1 &= ~((unsigned long long)m.z
                            | ((unsigned long long)m.w << 32));
                }
            }
            while (S1) {
                int r = __ffsll(S1) - 1;
                S1 &= S1 - 1;
                if ((A1 >> r) & 1ull) {
                    uint4 m = maskm[64 + r];
                    A1 &= ~((unsigned long long)m.z
                            | ((unsigned long long)m.w << 32));
                }
            }
            a0 = (unsigned)A0; a1 = (unsigned)(A0 >> 32);
            a2 = (unsigned)A1; a3 = (unsigned)(A1 >> 32);
        }
        a0 = __shfl_sync(FULL, a0, 0);
        a1 = __shfl_sync(FULL, a1, 0);
        a2 = __shfl_sync(FULL, a2, 0);
        a3 = __shfl_sync(FULL, a3, 0);

        const int p0 = __popc(a0), p1 = __popc(a1), p2 = __popc(a2);
        const int navail = p0 + p1 + p2 + __popc(a3);
        const int room = KMAX - kept;
        const int kn = min(room, navail);

        // ---- fully parallel extraction + epilogue (prefix popcount) ----
        unsigned aw[4] = {a0, a1, a2, a3};
        int bs_[4] = {0, p0, p0 + p1, p0 + p1 + p2};
        #pragma unroll
        for (int q = 0; q < SPT; q++) {
            if ((aw[q] >> lane) & 1u) {
                int pos = bs_[q] + __popc(aw[q] & ((1u << lane) - 1u));
                if (pos < kn) {
                    int r = lane + 32 * q;
                    float4 bb = rbox[r];
                    float  v  = __uint_as_float((unsigned)(ckey[r] >> 10));
                    fs[kept + pos] = v;
                    ((float4*)fb)[kept + pos] = bb;
                    kbox[kept + pos]  = bb;
                    karea[kept + pos] = rarea[r];
                    atomicAdd(&ghist[min((int)(v * 256.f), 255)], 1u);
                }
            }
        }
        kept += kn;
        __syncwarp();
    }

    for (int kk = kept + lane; kk < KMAX; kk += 32) fs[kk] = 0.0f;
}

// ---------------------------------------------------------------------------
// Stage 2: per image, exact rank-100. Histogram precomputed by decode.
// Warp-aggregated compaction + rank-by-count ordering.
// ---------------------------------------------------------------------------
__global__ __launch_bounds__(512)
void topk_kernel(float* __restrict__ out_boxes,
                 float* __restrict__ out_scores,
                 float* __restrict__ out_classes,
                 float* __restrict__ out_numdets,
                 int C)
{
    const int n    = blockIdx.x;
    const int tid  = threadIdx.x;
    const int lane = tid & 31;
    const int CK   = C * KMAX;                 // 8000
    const unsigned FULL = 0xffffffffu;

    __shared__ unsigned           hist[NBKT];
    __shared__ unsigned long long key[1024];
    __shared__ unsigned long long sorted[KMAX];
    __shared__ unsigned           scnt;

    // load precomputed per-image histogram
    if (tid < NBKT) hist[tid] = g_hist[n * NBKT + tid];
    if (tid == 0) scnt = 0u;
    if (tid < KMAX) sorted[tid] = 0ull;

    // batched score loads while histogram settles
    const float* src = g_flat_scores + (size_t)n * CK;
    const int NV4 = CK >> 2;                   // 2000
    float4 v4[4];
    #pragma unroll
    for (int u = 0; u < 4; u++) {
        int i4 = tid + 512 * u;
        v4[u] = (i4 < NV4) ? ((const float4*)src)[i4]
                           : make_float4(0.f, 0.f, 0.f, 0.f);
    }
    __syncthreads();

    int cnt_est;
    const int t_lo = pick_window_ge(hist, KMAX, lane, &cnt_est);  // all warps same

    // ---- warp-aggregated compaction ----
    #pragma unroll
    for (int u = 0; u < 4; u++) {
        float vv[4] = {v4[u].x, v4[u].y, v4[u].z, v4[u].w};
        #pragma unroll
        for (int j = 0; j < 4; j++) {
            float v = vv[j];
            bool take = (v > 0.f) && (min((int)(v * 256.f), 255) >= t_lo);
            unsigned m = __ballot_sync(FULL, take);
            if (m) {
                int leader = __ffs(m) - 1;
                unsigned base = 0;
                if (lane == leader) base = atomicAdd(&scnt, __popc(m));
                base = __shfl_sync(FULL, base, leader);
                if (take) {
                    unsigned p = base + __popc(m & ((1u << lane) - 1u));
                    if (p < 1024u) {
                        int i = 4 * (tid + 512 * u) + j;
                        key[p] = ((unsigned long long)__float_as_uint(v) << 13)
                               | (unsigned long long)(8191 - i);
                    }
                }
            }
        }
    }
    __syncthreads();
    const int cnt = min((int)scnt, 1024);

    // ---- rank-by-count ordering (no barriers inside) ----
    #pragma unroll
    for (int o = 0; o < 2; o++) {
        int own = tid + 512 * o;
        if (own < cnt) {
            unsigned long long mykey = key[own];
            int rank = 0;
            for (int s = 0; s < cnt; s++)
                rank += (key[s] > mykey) ? 1 : 0;
            if (rank < KMAX) sorted[rank] = mykey;
        }
    }
    __syncthreads();

    if (tid < KMAX) {
        unsigned long long kk = sorted[tid];
        bool valid = (kk != 0ull);
        float s = __uint_as_float((unsigned)(kk >> 13));
        int  fi = 8191 - (int)(kk & 8191ull);
        out_scores [n * KMAX + tid] = valid ? s : 0.f;
        out_classes[n * KMAX + tid] = valid ? (float)(fi / KMAX) : 0.f;
        float4 bb = make_float4(0.f, 0.f, 0.f, 0.f);
        if (valid) bb = ((const float4*)g_flat_boxes)[(size_t)n * CK + fi];
        ((float4*)out_boxes)[n * KMAX + tid] = bb;
    }
    if (tid == 0) out_numdets[n] = (float)min(cnt, KMAX);
}

// ---------------------------------------------------------------------------
extern "C" void kernel_launch(void* const* d_in, const int* in_sizes, int n_in,
                              void* d_out, int out_size)
{
    const float* rois   = (const float*)d_in[0];
    const float* conf   = (const float*)d_in[1];
    const float* deltas = (const float*)d_in[2];

    const int rois_elems = in_sizes[0];
    const int N = (out_size - rois_elems) / (6 * KMAX + 1);
    const int B = rois_elems / (4 * N);
    const int C = in_sizes[2] / ((size_t)N * B * 4);
    const int HW = in_sizes[3] / (3 * N);
    const int H = (int)(sqrt((double)HW) + 0.5);   // square image
    const float hm1 = (float)(H - 1);
    const float wm1 = (float)(H - 1);

    float* out         = (float*)d_out;
    float* out_boxes   = out;
    float* out_scores  = out + (size_t)N * KMAX * 4;
    float* out_classes = out + (size_t)N * KMAX * 5;
    float* out_numdets = out + (size_t)N * KMAX * 6;
    float* out_rois    = out + (size_t)N * KMAX * 6 + N;

    {
        dim3 grid((B + 31) / 32, (C + 31) / 32, N);
        dim3 block(32, 8);
        transpose_conf_kernel<<<grid, block>>>(conf, (const float4*)rois,
                                               (float4*)out_rois,
                                               rois_elems / 4, B, C);
    }
    {
        const int NC = N * C;
        decode_nms_kernel<<<(NC + WPB - 1) / WPB, 32 * WPB>>>(
            rois, deltas, B, C, NC, hm1, wm1);
    }
    topk_kernel<<<N, 512>>>(out_boxes, out_scores, out_classes,
                            out_numdets, C);
}

// round 13
// speedup vs baseline: 1.2692x; 1.0481x over previous
#include <cuda_runtime.h>
#include <cmath>

#define KMAX 100
#define NBKT 256
#define WPB  4      // warps per block, one (n,c) problem per warp (1 per SMSP)
#define TRN  128    // tranche size (candidates per NMS round)
#define SPT  4      // candidates per lane (TRN/32)

// Scratch (device globals — no allocation allowed).
__device__ float    g_flat_scores[16 * 128 * KMAX];     // [N][C][K]
__device__ float    g_flat_boxes [16 * 128 * KMAX * 4]; // [N][C][K][4]
__device__ float    g_conf_t     [16 * 128 * 1024];     // [N][C][B] transposed
__device__ unsigned g_hist       [16 * NBKT];           // per-image score hist

// ---------------------------------------------------------------------------
// Transpose conf [N][B][C+1] -> g_conf_t [N][C][B]  (drop background column)
// Also: rois passthrough + zero g_hist for the decode-built histograms.
// ---------------------------------------------------------------------------
__global__ void transpose_conf_kernel(const float* __restrict__ conf,
                                      const float4* __restrict__ rois4,
                                      float4* __restrict__ out_rois4,
                                      int rois_vec4, int B, int C)
{
    __shared__ float tile[32][33];
    const int n  = blockIdx.z;
    const int b0 = blockIdx.x * 32;
    const int c0 = blockIdx.y * 32;
    const int tx = threadIdx.x, ty = threadIdx.y;   // (32, 8)
    const int tid = ty * 32 + tx;

    // rois passthrough, spread over the by==0 slice of the grid
    if (blockIdx.y == 0) {
        int flat = (blockIdx.z * gridDim.x + blockIdx.x) * 256 + tid;
        if (flat < rois_vec4) out_rois4[flat] = rois4[flat];
    }
    // zero per-image histogram (one block per image does it)
    if (blockIdx.x == 0 && blockIdx.y == 0 && tid < NBKT)
        g_hist[n * NBKT + tid] = 0u;

    #pragma unroll
    for (int s = 0; s < 4; s++) {
        int b = b0 + ty + s * 8;
        int c = c0 + tx;
        if (b < B && c < C)
            tile[ty + s * 8][tx] = conf[((size_t)n * B + b) * (C + 1) + c];
    }
    __syncthreads();
    #pragma unroll
    for (int s = 0; s < 4; s++) {
        int c = c0 + ty + s * 8;
        int b = b0 + tx;
        if (b < B && c < C)
            g_conf_t[((size_t)n * C + c) * B + b] = tile[tx][ty + s * 8];
    }
}

// ---------------------------------------------------------------------------
// Warp-parallel threshold pickers over a 256-bucket histogram.
// ---------------------------------------------------------------------------
__device__ __forceinline__ int pick_window_le(const unsigned* hist, int t_hi,
                                              int limit, int lane, int* cnt_out)
{
    const unsigned FULL = 0xffffffffu;
    unsigned s = 0;
    #pragma unroll
    for (int m = 0; m < 8; m++) {
        int k = 8 * lane + m;
        if (k < t_hi) s += hist[k];
    }
    unsigned cum = s;                                // suffix-inclusive scan
    #pragma unroll
    for (int off = 1; off < 32; off <<= 1) {
        unsigned o = __shfl_down_sync(FULL, cum, off);
        if (lane + off < 32) cum += o;
    }
    unsigned bal = __ballot_sync(FULL, cum <= (unsigned)limit);
    int t_lo, cnt;
    int l0 = (bal == 0) ? 32 : (__ffs(bal) - 1);
    if (l0 == 0) {
        t_lo = 0;
        cnt  = (int)__shfl_sync(FULL, cum, 0);
    } else {
        int rl = (l0 - 1 < 31) ? l0 - 1 : 31;
        unsigned below = (l0 <= 31) ? __shfl_sync(FULL, cum, l0) : 0u;
        if (l0 == 32) below = 0u;
        int tl = (8 * l0 < 256) ? 8 * l0 : 256;
        unsigned run = below;
        if (lane == rl) {
            #pragma unroll
            for (int m = 7; m >= 0; m--) {
                int k = 8 * rl + m;
                unsigned h = (k < t_hi) ? hist[k] : 0u;
                if (run + h <= (unsigned)limit) { run += h; tl = k; }
                else break;
            }
        }
        t_lo = __shfl_sync(FULL, tl, rl);
        cnt  = (int)__shfl_sync(FULL, run, rl);
    }
    if (t_lo >= t_hi) {          // even one bucket overflows: take it anyway
        t_lo = t_hi - 1;
        cnt  = (int)hist[t_lo];
    }
    *cnt_out = cnt;
    return t_lo;
}

__device__ __forceinline__ int pick_window_ge(const unsigned* hist, int limit,
                                              int lane, int* cnt_out)
{
    const unsigned FULL = 0xffffffffu;
    unsigned s = 0;
    #pragma unroll
    for (int m = 0; m < 8; m++) s += hist[8 * lane + m];
    unsigned cum = s;
    #pragma unroll
    for (int off = 1; off < 32; off <<= 1) {
        unsigned o = __shfl_down_sync(FULL, cum, off);
        if (lane + off < 32) cum += o;
    }
    unsigned bal = __ballot_sync(FULL, cum >= (unsigned)limit);
    int t_lo, cnt;
    if (bal == 0) {
        t_lo = 0;
        cnt  = (int)__shfl_sync(FULL, cum, 0);
    } else {
        int lp = 31 - __clz(bal);
        unsigned below = (lp < 31) ? __shfl_sync(FULL, cum, lp + 1) : 0u;
        int tl = 8 * (lp + 1);
        unsigned run = below;
        if (lane == lp) {
            #pragma unroll
            for (int m = 7; m >= 0; m--) {
                run += hist[8 * lp + m];
                tl = 8 * lp + m;
                if (run >= (unsigned)limit) break;
            }
        }
        t_lo = __shfl_sync(FULL, tl, lp);
        cnt  = (int)__shfl_sync(FULL, run, lp);
    }
    *cnt_out = cnt;
    return t_lo;
}

// ---------------------------------------------------------------------------
// Stage 1: one WARP per (n, c); 4 warps per 128-thread CTA (1 per SMSP,
// grid = 160, occupancy 2 -> single wave, 136 SMs at pure chain latency).
// score load -> histogram -> threshold -> ballot compact (<=128) ->
// bitonic sort -> gather-decode (interleaved ranks) -> strict-upper-triangle
// suppression-mask matrix -> sparse lane-0 scan -> parallel extraction.
// ---------------------------------------------------------------------------
__global__ __launch_bounds__(32 * WPB)
void decode_nms_kernel(const float* __restrict__ rois,
                       const float* __restrict__ deltas,
                       int B, int C, int NC, float hm1, float wm1)
{
    const int w    = threadIdx.x >> 5;
    const int lane = threadIdx.x & 31;
    const int pid  = blockIdx.x * WPB + w;
    if (pid >= NC) return;
    const int n = pid / C;
    const int c = pid % C;
    const unsigned FULL = 0xffffffffu;

    __shared__ unsigned           hist_s [WPB][NBKT];
    __shared__ unsigned long long ckey_s [WPB][TRN];
    __shared__ float4             rbox_s [WPB][TRN];
    __shared__ float              rarea_s[WPB][TRN];
    __shared__ uint4              mask_s [WPB][TRN];
    __shared__ float4             kbox_s [WPB][KMAX];
    __shared__ float              karea_s[WPB][KMAX];

    unsigned*           hist  = hist_s [w];
    unsigned long long* ckey  = ckey_s [w];
    float4*             rbox  = rbox_s [w];
    float*              rarea = rarea_s[w];
    uint4*              maskm = mask_s [w];
    float4*             kbox  = kbox_s [w];
    float*              karea = karea_s[w];

    for (int i = lane; i < NBKT; i += 32) hist[i] = 0u;
    __syncwarp();

    // ---- coalesced score load (transposed conf), MLP=8 ----
    const float* csrc = g_conf_t + ((size_t)n * C + c) * B;
    const int NV4 = B >> 2;          // B divisible by 4 (B=1000)
    float rs[32];
    #pragma unroll
    for (int u = 0; u < 8; u++) {
        int i4 = lane + 32 * u;
        float4 v = make_float4(0.f, 0.f, 0.f, 0.f);
        if (i4 < NV4) v = ((const float4*)csrc)[i4];
        rs[4*u+0] = (v.x > 0.05f) ? v.x : 0.f;
        rs[4*u+1] = (v.y > 0.05f) ? v.y : 0.f;
        rs[4*u+2] = (v.z > 0.05f) ? v.z : 0.f;
        rs[4*u+3] = (v.w > 0.05f) ? v.w : 0.f;
    }
    // b index of rs[e]: e = 4u + j  ->  b = 128*u + 4*lane + j

    #pragma unroll
    for (int e = 0; e < 32; e++) {
        float v = rs[e];
        if (v > 0.f) atomicAdd(&hist[min((int)(v * 256.f), 255)], 1u);
    }
    __syncwarp();

    float* fs = g_flat_scores + ((size_t)n * C + c) * KMAX;
    float* fb = g_flat_boxes  + ((size_t)n * C + c) * KMAX * 4;
    unsigned* ghist = g_hist + n * NBKT;

    int kept = 0;
    int t_hi = NBKT;

    while (kept < KMAX && t_hi > 0) {
        int cnt;
        const int t_lo = pick_window_le(hist, t_hi, TRN, lane, &cnt);
        const int w_hi = t_hi;          // window = [t_lo, w_hi)
        t_hi = t_lo;
        if (cnt > TRN) cnt = TRN;
        if (cnt == 0) continue;

        // ---- ballot compaction ----
        unsigned base = 0;
        #pragma unroll
        for (int e = 0; e < 32; e++) {
            float v = rs[e];
            int bk = (v > 0.f) ? min((int)(v * 256.f), 255) : -1;
            bool take = (bk >= t_lo) && (bk < w_hi);
            unsigned m = __ballot_sync(FULL, take);
            if (take) {
                unsigned pos = base + __popc(m & ((1u << lane) - 1u));
                if (pos < (unsigned)TRN) {
                    int b = 128 * (e >> 2) + 4 * lane + (e & 3);
                    ckey[pos] = ((unsigned long long)__float_as_uint(v) << 10)
                              | (unsigned long long)(1023 - b);
                }
            }
            base += __popc(m);
        }
        __syncwarp();

        int P = 1; while (P < cnt) P <<= 1;
        for (int i = cnt + lane; i < P; i += 32) ckey[i] = 0ull;
        __syncwarp();

        // ---- bitonic sort desc by (score, ~b) ----
        for (int k = 2; k <= P; k <<= 1) {
            for (int j = k >> 1; j > 0; j >>= 1) {
                for (int p = lane; p < (P >> 1); p += 32) {
                    int i = ((p & ~(j - 1)) << 1) | (p & (j - 1));
                    int l = i | j;
                    unsigned long long a = ckey[i], bb = ckey[l];
                    bool desc = ((i & k) == 0);
                    if (desc ? (a < bb) : (a > bb)) { ckey[i] = bb; ckey[l] = a; }
                }
                __syncwarp();
            }
        }

        // ---- gather-decode: INTERLEAVED ranks, lane owns r = lane + 32q ----
        float by1[SPT], bx1[SPT], by2[SPT], bx2[SPT], bar_[SPT];
        unsigned alive = 0;
        #pragma unroll
        for (int q = 0; q < SPT; q++) {
            int r = lane + 32 * q;
            float yy1 = 0.f, xx1 = 0.f, yy2 = 0.f, xx2 = 0.f, ar = 0.f;
            if (r < cnt) {
                unsigned long long key = ckey[r];
                int b = 1023 - (int)(key & 1023ull);
                float4 rr = ((const float4*)rois)[(size_t)n * B + b];
                float w0 = rr.w - rr.y + 1.0f;
                float h0 = rr.z - rr.x + 1.0f;
                float x0 = rr.y + 0.5f * w0;
                float y0 = rr.x + 0.5f * h0;
                float4 d = ((const float4*)deltas)[((size_t)n * B + b) * C + c];
                float cx = (d.x * 0.1f) * w0 + x0;
                float cy = (d.y * 0.1f) * h0 + y0;
                float ww = __expf(d.z * 0.2f) * w0;
                float hh = __expf(d.w * 0.2f) * h0;
                xx1 = fminf(fmaxf(cx - 0.5f * ww, 0.0f), wm1);
                yy1 = fminf(fmaxf(cy - 0.5f * hh, 0.0f), hm1);
                xx2 = fminf(fmaxf(cx + 0.5f * ww, 0.0f), wm1);
                yy2 = fminf(fmaxf(cy + 0.5f * hh, 0.0f), hm1);
                ar  = (yy2 - yy1) * (xx2 - xx1);
                rbox[r]  = make_float4(yy1, xx1, yy2, xx2);
                rarea[r] = ar;
                alive |= (1u << q);
            }
            by1[q] = yy1; bx1[q] = xx1; by2[q] = yy2; bx2[q] = xx2; bar_[q] = ar;
        }
        __syncwarp();

        // ---- later tranches: pre-suppress vs already-kept boxes ----
        for (int kk = 0; kk < kept; kk++) {
            float4 kb = kbox[kk];
            float  ka = karea[kk];
            #pragma unroll
            for (int q = 0; q < SPT; q++) {
                if (alive & (1u << q)) {
                    float iy1 = fmaxf(kb.x, by1[q]);
                    float ix1 = fmaxf(kb.y, bx1[q]);
                    float iy2 = fminf(kb.z, by2[q]);
                    float ix2 = fminf(kb.w, bx2[q]);
                    float it  = fmaxf(iy2 - iy1, 0.f) * fmaxf(ix2 - ix1, 0.f);
                    float un  = fmaxf(ka + bar_[q] - it, 1e-8f);
                    if (it > 0.5f * un) alive &= ~(1u << q);
                }
            }
        }

        // ---- strict-upper-triangle suppression-mask matrix (no self-bit) ----
        unsigned acc[SPT][4];
        #pragma unroll
        for (int q = 0; q < SPT; q++) {
            acc[q][0] = 0u; acc[q][1] = 0u; acc[q][2] = 0u; acc[q][3] = 0u;
        }
        #pragma unroll
        for (int wb = 0; wb < 4; wb++) {
            if (32 * wb >= cnt) break;
            #pragma unroll 4
            for (int sb = 0; sb < 32; sb++) {
                int s = 32 * wb + sb;
                float4 bs = rbox[s];          // broadcast LDS
                float  as_ = rarea[s];
                #pragma unroll
                for (int q = 0; q <= wb && q < SPT; q++) {
                    float iy1 = fmaxf(bs.x, by1[q]);
                    float ix1 = fmaxf(bs.y, bx1[q]);
                    float iy2 = fminf(bs.z, by2[q]);
                    float ix2 = fminf(bs.w, bx2[q]);
                    float it  = fmaxf(iy2 - iy1, 0.f) * fmaxf(ix2 - ix1, 0.f);
                    float un  = fmaxf(as_ + bar_[q] - it, 1e-8f);
                    if (it > 0.5f * un) acc[q][wb] |= (1u << sb);
                }
            }
        }
        // clear <= diagonal bits in the diagonal block (strict upper triangle)
        #pragma unroll
        for (int q = 0; q < SPT; q++)
            acc[q][q] &= ~((2u << lane) - 1u);

        // suppressing-row set (rows with any mask bit) + conditional store
        unsigned srow[SPT];
        #pragma unroll
        for (int q = 0; q < SPT; q++) {
            bool nz = (acc[q][0] | acc[q][1] | acc[q][2] | acc[q][3]) != 0u;
            srow[q] = __ballot_sync(FULL, nz);
            if (nz) maskm[lane + 32 * q] =
                make_uint4(acc[q][0], acc[q][1], acc[q][2], acc[q][3]);
        }
        __syncwarp();

        // ---- alive words via ballot (word q = ranks [32q, 32q+32)) ----
        unsigned a0 = __ballot_sync(FULL, (alive >> 0) & 1u);
        unsigned a1 = __ballot_sync(FULL, (alive >> 1) & 1u);
        unsigned a2 = __ballot_sync(FULL, (alive >> 2) & 1u);
        unsigned a3 = __ballot_sync(FULL, (alive >> 3) & 1u);

        // ---- SPARSE scan on lane 0: only suppressing rows, ascending ----
        if (lane == 0) {
            unsigned long long A0 = (unsigned long long)a0
                                  | ((unsigned long long)a1 << 32);
            unsigned long long A1 = (unsigned long long)a2
                                  | ((unsigned long long)a3 << 32);
            unsigned long long S0 = (unsigned long long)srow[0]
                                  | ((unsigned long long)srow[1] << 32);
            unsigned long long S1 = (unsigned long long)srow[2]
                                  | ((unsigned long long)srow[3] << 32);
            while (S0) {
                int r = __ffsll(S0) - 1;
                S0 &= S0 - 1;
                if ((A0 >> r) & 1ull) {
                    uint4 m = maskm[r];
                    A0 &= ~((unsigned long long)m.x
                            | ((unsigned long long)m.y << 32));
                    A1 &= ~((unsigned long long)m.z
                            | ((unsigned long long)m.w << 32));
                }
            }
            while (S1) {
                int r = __ffsll(S1) - 1;
                S1 &= S1 - 1;
                if ((A1 >> r) & 1ull) {
                    uint4 m = maskm[64 + r];
                    A1 &= ~((unsigned long long)m.z
                            | ((unsigned long long)m.w << 32));
                }
            }
            a0 = (unsigned)A0; a1 = (unsigned)(A0 >> 32);
            a2 = (unsigned)A1; a3 = (unsigned)(A1 >> 32);
        }
        a0 = __shfl_sync(FULL, a0, 0);
        a1 = __shfl_sync(FULL, a1, 0);
        a2 = __shfl_sync(FULL, a2, 0);
        a3 = __shfl_sync(FULL, a3, 0);

        const int p0 = __popc(a0), p1 = __popc(a1), p2 = __popc(a2);
        const int navail = p0 + p1 + p2 + __popc(a3);
        const int room = KMAX - kept;
        const int kn = min(room, navail);

        // ---- fully parallel extraction + epilogue (prefix popcount) ----
        unsigned aw[4] = {a0, a1, a2, a3};
        int bs_[4] = {0, p0, p0 + p1, p0 + p1 + p2};
        #pragma unroll
        for (int q = 0; q < SPT; q++) {
            if ((aw[q] >> lane) & 1u) {
                int pos = bs_[q] + __popc(aw[q] & ((1u << lane) - 1u));
                if (pos < kn) {
                    int r = lane + 32 * q;
                    float4 bb = rbox[r];
                    float  v  = __uint_as_float((unsigned)(ckey[r] >> 10));
                    fs[kept + pos] = v;
                    ((float4*)fb)[kept + pos] = bb;
                    kbox[kept + pos]  = bb;
                    karea[kept + pos] = rarea[r];
                    atomicAdd(&ghist[min((int)(v * 256.f), 255)], 1u);
                }
            }
        }
        kept += kn;
        __syncwarp();
    }

    for (int kk = kept + lane; kk < KMAX; kk += 32) fs[kk] = 0.0f;
}

// ---------------------------------------------------------------------------
// Stage 2: per image, exact rank-100. Histogram precomputed by decode.
// Warp-aggregated compaction + rank-by-count ordering.
// ---------------------------------------------------------------------------
__global__ __launch_bounds__(512)
void topk_kernel(float* __restrict__ out_boxes,
                 float* __restrict__ out_scores,
                 float* __restrict__ out_classes,
                 float* __restrict__ out_numdets,
                 int C)
{
    const int n    = blockIdx.x;
    const int tid  = threadIdx.x;
    const int lane = tid & 31;
    const int CK   = C * KMAX;                 // 8000
    const unsigned FULL = 0xffffffffu;

    __shared__ unsigned           hist[NBKT];
    __shared__ unsigned long long key[1024];
    __shared__ unsigned long long sorted[KMAX];
    __shared__ unsigned           scnt;

    // load precomputed per-image histogram
    if (tid < NBKT) hist[tid] = g_hist[n * NBKT + tid];
    if (tid == 0) scnt = 0u;
    if (tid < KMAX) sorted[tid] = 0ull;

    // batched score loads while histogram settles
    const float* src = g_flat_scores + (size_t)n * CK;
    const int NV4 = CK >> 2;                   // 2000
    float4 v4[4];
    #pragma unroll
    for (int u = 0; u < 4; u++) {
        int i4 = tid + 512 * u;
        v4[u] = (i4 < NV4) ? ((const float4*)src)[i4]
                           : make_float4(0.f, 0.f, 0.f, 0.f);
    }
    __syncthreads();

    int cnt_est;
    const int t_lo = pick_window_ge(hist, KMAX, lane, &cnt_est);  // all warps same

    // ---- warp-aggregated compaction ----
    #pragma unroll
    for (int u = 0; u < 4; u++) {
        float vv[4] = {v4[u].x, v4[u].y, v4[u].z, v4[u].w};
        #pragma unroll
        for (int j = 0; j < 4; j++) {
            float v = vv[j];
            bool take = (v > 0.f) && (min((int)(v * 256.f), 255) >= t_lo);
            unsigned m = __ballot_sync(FULL, take);
            if (m) {
                int leader = __ffs(m) - 1;
                unsigned base = 0;
                if (lane == leader) base = atomicAdd(&scnt, __popc(m));
                base = __shfl_sync(FULL, base, leader);
                if (take) {
                    unsigned p = base + __popc(m & ((1u << lane) - 1u));
                    if (p < 1024u) {
                        int i = 4 * (tid + 512 * u) + j;
                        key[p] = ((unsigned long long)__float_as_uint(v) << 13)
                               | (unsigned long long)(8191 - i);
                    }
                }
            }
        }
    }
    __syncthreads();
    const int cnt = min((int)scnt, 1024);

    // ---- rank-by-count ordering (no barriers inside) ----
    #pragma unroll
    for (int o = 0; o < 2; o++) {
        int own = tid + 512 * o;
        if (own < cnt) {
            unsigned long long mykey = key[own];
            int rank = 0;
            for (int s = 0; s < cnt; s++)
                rank += (key[s] > mykey) ? 1 : 0;
            if (rank < KMAX) sorted[rank] = mykey;
        }
    }
    __syncthreads();

    if (tid < KMAX) {
        unsigned long long kk = sorted[tid];
        bool valid = (kk != 0ull);
        float s = __uint_as_float((unsigned)(kk >> 13));
        int  fi = 8191 - (int)(kk & 8191ull);
        out_scores [n * KMAX + tid] = valid ? s : 0.f;
        out_classes[n * KMAX + tid] = valid ? (float)(fi / KMAX) : 0.f;
        float4 bb = make_float4(0.f, 0.f, 0.f, 0.f);
        if (valid) bb = ((const float4*)g_flat_boxes)[(size_t)n * CK + fi];
        ((float4*)out_boxes)[n * KMAX + tid] = bb;
    }
    if (tid == 0) out_numdets[n] = (float)min(cnt, KMAX);
}

// ---------------------------------------------------------------------------
extern "C" void kernel_launch(void* const* d_in, const int* in_sizes, int n_in,
                              void* d_out, int out_size)
{
    const float* rois   = (const float*)d_in[0];
    const float* conf   = (const float*)d_in[1];
    const float* deltas = (const float*)d_in[2];

    const int rois_elems = in_sizes[0];
    const int N = (out_size - rois_elems) / (6 * KMAX + 1);
    const int B = rois_elems / (4 * N);
    const int C = in_sizes[2] / ((size_t)N * B * 4);
    const int HW = in_sizes[3] / (3 * N);
    const int H = (int)(sqrt((double)HW) + 0.5);   // square image
    const float hm1 = (float)(H - 1);
    const float wm1 = (float)(H - 1);

    float* out         = (float*)d_out;
    float* out_boxes   = out;
    float* out_scores  = out + (size_t)N * KMAX * 4;
    float* out_classes = out + (size_t)N * KMAX * 5;
    float* out_numdets = out + (size_t)N * KMAX * 6;
    float* out_rois    = out + (size_t)N * KMAX * 6 + N;

    {
        dim3 grid((B + 31) / 32, (C + 31) / 32, N);
        dim3 block(32, 8);
        transpose_conf_kernel<<<grid, block>>>(conf, (const float4*)rois,
                                               (float4*)out_rois,
                                               rois_elems / 4, B, C);
    }
    {
        const int NC = N * C;
        decode_nms_kernel<<<(NC + WPB - 1) / WPB, 32 * WPB>>>(
            rois, deltas, B, C, NC, hm1, wm1);
    }
    topk_kernel<<<N, 512>>>(out_boxes, out_scores, out_classes,
                            out_numdets, C);
}